// round 2
// baseline (speedup 1.0000x reference)
#include <cuda_runtime.h>
#include <cuda_fp16.h>
#include <cstdint>

// Problem dims (fixed): x [8,2048,2048] -> N=16384 rows, D=2048, R=256
#define NROWS 16384
#define DDIM  2048
#define RDIM  256

// Scratch (device globals: allocation inside kernel_launch is forbidden)
__device__ __half g_wsT_in [RDIM * DDIM];          // W_in^T  sparsified: [M=256 ][K=2048]
__device__ __half g_wsT_out[DDIM * RDIM];          // W_out^T sparsified: [M=2048][K=256 ]
__device__ __half g_h      [(size_t)NROWS * RDIM]; // intermediate h (fp16)

// ---------------------------------------------------------------------------
// 2:4 soft-threshold + scale + fp16 cast + transpose.
// w: [K][M] fp32, groups of 4 along M (last dim). Out wsT: [M][K] fp16.
// ---------------------------------------------------------------------------
__global__ void sparsify_kernel(const float* __restrict__ w,
                                const float* __restrict__ scale,
                                __half* __restrict__ wsT, int K, int M)
{
    int idx = blockIdx.x * blockDim.x + threadIdx.x;
    int gpr = M >> 2;
    if (idx >= K * gpr) return;
    int row = idx / gpr;              // k
    int g   = idx - row * gpr;        // group along M
    float4 v = *reinterpret_cast<const float4*>(w + (size_t)row * M + g * 4);
    float a0 = fabsf(v.x), a1 = fabsf(v.y), a2 = fabsf(v.z), a3 = fabsf(v.w);
    float m01 = fminf(a0, a1), M01 = fmaxf(a0, a1);
    float m23 = fminf(a2, a3), M23 = fmaxf(a2, a3);
    float t = fminf(fmaxf(m01, m23), fminf(M01, M23));  // 2nd smallest of 4
    float s = scale[0];
    float o0 = copysignf(fmaxf(a0 - t, 0.f) * s, v.x);
    float o1 = copysignf(fmaxf(a1 - t, 0.f) * s, v.y);
    float o2 = copysignf(fmaxf(a2 - t, 0.f) * s, v.z);
    float o3 = copysignf(fmaxf(a3 - t, 0.f) * s, v.w);
    int m0 = g * 4;
    wsT[(size_t)(m0 + 0) * K + row] = __float2half(o0);
    wsT[(size_t)(m0 + 1) * K + row] = __float2half(o1);
    wsT[(size_t)(m0 + 2) * K + row] = __float2half(o2);
    wsT[(size_t)(m0 + 3) * K + row] = __float2half(o3);
}

// ---------------------------------------------------------------------------
// HMMA GEMM:  Out[N][M] = A[N][K] (fp16-cast) * BT[M][K]^T, fp32 accum.
// 128x128x32 block tile, 8 warps (32x64 warp tiles), m16n8k16 mma.
// 2-stage double-buffered smem; cp.async for fp16 operands, register
// prefetch + convert for the fp32 A in GEMM1.
// ---------------------------------------------------------------------------
__device__ __forceinline__ void ldsm_x4(uint32_t& r0, uint32_t& r1,
                                        uint32_t& r2, uint32_t& r3, uint32_t addr)
{
    asm volatile("ldmatrix.sync.aligned.m8n8.x4.shared.b16 {%0,%1,%2,%3}, [%4];\n"
                 : "=r"(r0), "=r"(r1), "=r"(r2), "=r"(r3) : "r"(addr));
}

__device__ __forceinline__ void mma16816(float* c, const uint32_t* a, const uint32_t* b)
{
    asm volatile("mma.sync.aligned.m16n8k16.row.col.f32.f16.f16.f32 "
                 "{%0,%1,%2,%3}, {%4,%5,%6,%7}, {%8,%9}, {%0,%1,%2,%3};\n"
                 : "+f"(c[0]), "+f"(c[1]), "+f"(c[2]), "+f"(c[3])
                 : "r"(a[0]), "r"(a[1]), "r"(a[2]), "r"(a[3]), "r"(b[0]), "r"(b[1]));
}

__device__ __forceinline__ void cp_async16(void* smem, const void* gmem)
{
    uint32_t s = (uint32_t)__cvta_generic_to_shared(smem);
    asm volatile("cp.async.cg.shared.global [%0], [%1], 16;\n" :: "r"(s), "l"(gmem));
}

template<bool A_HALF, bool OUT_HALF>
__global__ void __launch_bounds__(256)
gemm_tn(const void* __restrict__ Ap, const __half* __restrict__ BT,
        const float* __restrict__ bias, void* __restrict__ Outp,
        int N, int K, int M)
{
    constexpr int BN = 128, BM = 128, BK = 32, SA = 40; // SA: smem stride (halves)
    __shared__ __half As[2][BN * SA];
    __shared__ __half Bs[2][BM * SA];

    const int tid  = threadIdx.x;
    const int lane = tid & 31;
    const int wid  = tid >> 5;
    const int bn = blockIdx.y * BN;
    const int bm = blockIdx.x * BM;
    const int wrow = (wid >> 1) * 32;
    const int wcol = (wid & 1) * 64;

    float acc[2][8][4];
    #pragma unroll
    for (int i = 0; i < 2; i++)
        #pragma unroll
        for (int j = 0; j < 8; j++)
            #pragma unroll
            for (int q = 0; q < 4; q++) acc[i][j][q] = 0.f;

    // ldmatrix lane mappings
    const int a_r = lane & 15;
    const int a_c = (lane >> 4) * 8;
    const int b_g = lane >> 3;
    const int b_r = (lane & 7) + (b_g >> 1) * 8;
    const int b_c = (b_g & 1) * 8;

    // per-thread tile-load coordinates
    // fp16 tile: 2 x 16B chunks/thread: idx=tid*2+i -> row=idx>>2, col8=idx&3
    // fp32 A tile: 4 x float4/thread:   idx=tid*4+i -> row=idx>>3, col4=idx&7

    auto issueB = [&](int st, int k0) {
        #pragma unroll
        for (int i = 0; i < 2; i++) {
            int idx = tid * 2 + i, r = idx >> 2, c8 = idx & 3;
            cp_async16(&Bs[st][r * SA + c8 * 8],
                       BT + (size_t)(bm + r) * K + k0 + c8 * 8);
        }
    };
    auto issueA_half = [&](int st, int k0) {
        const __half* A = (const __half*)Ap;
        #pragma unroll
        for (int i = 0; i < 2; i++) {
            int idx = tid * 2 + i, r = idx >> 2, c8 = idx & 3;
            cp_async16(&As[st][r * SA + c8 * 8],
                       A + (size_t)(bn + r) * K + k0 + c8 * 8);
        }
    };
    auto ldA_f32 = [&](float4* av, int k0) {
        const float* A = (const float*)Ap;
        #pragma unroll
        for (int i = 0; i < 4; i++) {
            int idx = tid * 4 + i, r = idx >> 3, c4 = idx & 7;
            av[i] = *reinterpret_cast<const float4*>(A + (size_t)(bn + r) * K + k0 + c4 * 4);
        }
    };
    auto stA_f32 = [&](const float4* av, int st) {
        #pragma unroll
        for (int i = 0; i < 4; i++) {
            int idx = tid * 4 + i, r = idx >> 3, c4 = idx & 7;
            __half2 h0 = __floats2half2_rn(av[i].x, av[i].y);
            __half2 h1 = __floats2half2_rn(av[i].z, av[i].w);
            *reinterpret_cast<__half2*>(&As[st][r * SA + c4 * 4 + 0]) = h0;
            *reinterpret_cast<__half2*>(&As[st][r * SA + c4 * 4 + 2]) = h1;
        }
    };

    const int T = K / BK;

    // ---- prologue: fill stage 0 ----
    if (A_HALF) {
        issueA_half(0, 0);
    } else {
        float4 av0[4];
        ldA_f32(av0, 0);
        stA_f32(av0, 0);
    }
    issueB(0, 0);
    asm volatile("cp.async.commit_group;\n");

    for (int kt = 0; kt < T; kt++) {
        const int cur = kt & 1, nxt = cur ^ 1;
        const bool has_next = (kt + 1) < T;
        float4 av[4];
        if (has_next) {
            if (A_HALF) issueA_half(nxt, (kt + 1) * BK);
            else        ldA_f32(av, (kt + 1) * BK);
            issueB(nxt, (kt + 1) * BK);
            asm volatile("cp.async.commit_group;\n");
            asm volatile("cp.async.wait_group 1;\n");
        } else {
            asm volatile("cp.async.wait_group 0;\n");
        }
        __syncthreads();

        // ---- compute from stage cur ----
        #pragma unroll
        for (int ks = 0; ks < BK; ks += 16) {
            uint32_t af[2][4];
            #pragma unroll
            for (int mt = 0; mt < 2; mt++) {
                uint32_t addr = (uint32_t)__cvta_generic_to_shared(
                    &As[cur][(wrow + mt * 16 + a_r) * SA + ks + a_c]);
                ldsm_x4(af[mt][0], af[mt][1], af[mt][2], af[mt][3], addr);
            }
            uint32_t bf[8][2];
            #pragma unroll
            for (int p = 0; p < 4; p++) {
                uint32_t r0, r1, r2, r3;
                uint32_t addr = (uint32_t)__cvta_generic_to_shared(
                    &Bs[cur][(wcol + p * 16 + b_r) * SA + ks + b_c]);
                ldsm_x4(r0, r1, r2, r3, addr);
                bf[2 * p + 0][0] = r0; bf[2 * p + 0][1] = r1;
                bf[2 * p + 1][0] = r2; bf[2 * p + 1][1] = r3;
            }
            #pragma unroll
            for (int mt = 0; mt < 2; mt++)
                #pragma unroll
                for (int nt = 0; nt < 8; nt++)
                    mma16816(acc[mt][nt], af[mt], bf[nt]);
        }

        if (has_next && !A_HALF) stA_f32(av, nxt);
        __syncthreads();
    }

    // ---- epilogue: bias + store ----
    const int er = lane >> 2;
    const int ec = (lane & 3) * 2;
    #pragma unroll
    for (int mt = 0; mt < 2; mt++) {
        #pragma unroll
        for (int nt = 0; nt < 8; nt++) {
            int col = bm + wcol + nt * 8 + ec;
            float b0 = bias[col], b1 = bias[col + 1];
            int row0 = bn + wrow + mt * 16 + er;
            if (OUT_HALF) {
                __half* Out = (__half*)Outp;
                __half2 v0 = __floats2half2_rn(acc[mt][nt][0] + b0, acc[mt][nt][1] + b1);
                __half2 v1 = __floats2half2_rn(acc[mt][nt][2] + b0, acc[mt][nt][3] + b1);
                *reinterpret_cast<__half2*>(Out + (size_t)row0 * M + col) = v0;
                *reinterpret_cast<__half2*>(Out + (size_t)(row0 + 8) * M + col) = v1;
            } else {
                float* Out = (float*)Outp;
                float2 v0 = make_float2(acc[mt][nt][0] + b0, acc[mt][nt][1] + b1);
                float2 v1 = make_float2(acc[mt][nt][2] + b0, acc[mt][nt][3] + b1);
                *reinterpret_cast<float2*>(Out + (size_t)row0 * M + col) = v0;
                *reinterpret_cast<float2*>(Out + (size_t)(row0 + 8) * M + col) = v1;
            }
        }
    }
}

// ---------------------------------------------------------------------------
// Launch. Inputs: x, weight_in, weight_out, bias_in, bias_out, scale_in, scale_out.
// ---------------------------------------------------------------------------
extern "C" void kernel_launch(void* const* d_in, const int* in_sizes, int n_in,
                              void* d_out, int out_size)
{
    const float* x        = (const float*)d_in[0];
    const float* w_in     = (const float*)d_in[1];
    const float* w_out    = (const float*)d_in[2];
    const float* bias_in  = (const float*)d_in[3];
    const float* bias_out = (const float*)d_in[4];
    const float* s_in     = (const float*)d_in[5];
    const float* s_out    = (const float*)d_in[6];

    __half *wsT_in, *wsT_out, *hbuf;
    cudaGetSymbolAddress((void**)&wsT_in,  g_wsT_in);
    cudaGetSymbolAddress((void**)&wsT_out, g_wsT_out);
    cudaGetSymbolAddress((void**)&hbuf,    g_h);

    // 1) sparsify + scale + transpose both weights
    {
        int ngroups = DDIM * (RDIM / 4);
        sparsify_kernel<<<(ngroups + 255) / 256, 256>>>(w_in, s_in, wsT_in, DDIM, RDIM);
    }
    {
        int ngroups = RDIM * (DDIM / 4);
        sparsify_kernel<<<(ngroups + 255) / 256, 256>>>(w_out, s_out, wsT_out, RDIM, DDIM);
    }
    // 2) GEMM1: h[N][256] = x * wsT_in^T (+bias_in), fp16 out
    {
        dim3 grid(RDIM / 128, NROWS / 128);
        gemm_tn<false, true><<<grid, 256>>>(x, wsT_in, bias_in, hbuf, NROWS, DDIM, RDIM);
    }
    // 3) GEMM2: y[N][2048] = h * wsT_out^T (+bias_out), fp32 out
    {
        dim3 grid(DDIM / 128, NROWS / 128);
        gemm_tn<true, false><<<grid, 256>>>(hbuf, wsT_out, bias_out, d_out, NROWS, RDIM, DDIM);
    }
}